// round 2
// baseline (speedup 1.0000x reference)
#include <cuda_runtime.h>
#include <math.h>
#include <stdint.h>

// Problem constants (fixed by the reference)
#define BZ 4
#define SZ 2048
#define DD 768
#define HH 3072
#define EE 8
#define KK 2
#define NTOK (BZ*SZ)          // 8192 tokens
#define NENT (NTOK*KK)        // 16384 routing entries
#define CAP  1536             // int(B*S/E * 1.5)
#define ROWS_MAX (EE*CAP)     // 12288 kept (token,expert) pairs max

// ---------------- scratch (device globals: no allocation allowed) ----------
__device__ int   g_topk_e[NENT];
__device__ float g_topk_p[NENT];
__device__ int   g_rows[ROWS_MAX];        // per-expert token lists (e*CAP + pos)
__device__ int   g_cnt[EE];               // kept count per expert (<= CAP)
__device__ int   g_slot[NENT];            // entry -> e*CAP+pos, or -1 if dropped
__device__ float g_gate[NENT];            // entry -> combine weight (0 if dropped)
__device__ float g_Hbuf[(size_t)ROWS_MAX * HH];   // gelu(x@w1+b1), 151 MB
__device__ float g_Ybuf[(size_t)ROWS_MAX * DD];   // h@w2+b2, 37.7 MB

// ---------------- packed f32x2 helpers (Blackwell) -------------------------
__device__ __forceinline__ uint64_t pk2(float lo, float hi) {
    uint64_t r;
    asm("mov.b64 %0, {%1, %2};" : "=l"(r) : "f"(lo), "f"(hi));
    return r;
}
__device__ __forceinline__ void unpk2(uint64_t v, float& lo, float& hi) {
    asm("mov.b64 {%0, %1}, %2;" : "=f"(lo), "=f"(hi) : "l"(v));
}
#define FMA_F32X2(acc, a, b) \
    asm("fma.rn.f32x2 %0, %1, %2, %0;" : "+l"(acc) : "l"(a), "l"(b))

// ---------------- 1) router: logits -> softmax -> top2 -> renorm -----------
__global__ void router_kernel(const float* __restrict__ x,
                              const float* __restrict__ Wr) {
    int warp = threadIdx.x >> 5;
    int lane = threadIdx.x & 31;
    int t = blockIdx.x * 8 + warp;
    if (t >= NTOK) return;
    const float* xr = x + (size_t)t * DD;
    float acc[EE];
#pragma unroll
    for (int e = 0; e < EE; e++) acc[e] = 0.f;
    for (int i = lane; i < DD; i += 32) {
        float xv = xr[i];
        const float4* wr4 = reinterpret_cast<const float4*>(Wr + i * EE);
        float4 w0 = wr4[0], w1 = wr4[1];
        acc[0] += xv * w0.x; acc[1] += xv * w0.y;
        acc[2] += xv * w0.z; acc[3] += xv * w0.w;
        acc[4] += xv * w1.x; acc[5] += xv * w1.y;
        acc[6] += xv * w1.z; acc[7] += xv * w1.w;
    }
#pragma unroll
    for (int e = 0; e < EE; e++) {
#pragma unroll
        for (int o = 16; o > 0; o >>= 1)
            acc[e] += __shfl_xor_sync(0xffffffffu, acc[e], o);
    }
    if (lane == 0) {
        float m = acc[0];
#pragma unroll
        for (int e = 1; e < EE; e++) m = fmaxf(m, acc[e]);
        float p[EE]; float s = 0.f;
#pragma unroll
        for (int e = 0; e < EE; e++) { p[e] = expf(acc[e] - m); s += p[e]; }
        float inv = 1.f / s;
#pragma unroll
        for (int e = 0; e < EE; e++) p[e] *= inv;
        int i0 = 0;
#pragma unroll
        for (int e = 1; e < EE; e++) if (p[e] > p[i0]) i0 = e;   // first-max tie rule
        int i1 = -1;
#pragma unroll
        for (int e = 0; e < EE; e++) {
            if (e == i0) continue;
            if (i1 < 0 || p[e] > p[i1]) i1 = e;
        }
        float ps = 1.f / (p[i0] + p[i1]);
        g_topk_e[2 * t + 0] = i0; g_topk_p[2 * t + 0] = p[i0] * ps;
        g_topk_e[2 * t + 1] = i1; g_topk_p[2 * t + 1] = p[i1] * ps;
    }
}

// ---------------- 2) capacity assignment (exact flat-order semantics) ------
#define ATH 512
#define EPT (NENT / ATH)   // 32 entries per thread
__global__ void assign_kernel() {
    __shared__ int sh[EE][ATH];
    int t = threadIdx.x;
    int loc[EE];
#pragma unroll
    for (int e = 0; e < EE; e++) loc[e] = 0;
    int start = t * EPT;
    for (int i = 0; i < EPT; i++) loc[g_topk_e[start + i]]++;
#pragma unroll
    for (int e = 0; e < EE; e++) sh[e][t] = loc[e];
    __syncthreads();
    if (t < EE) {
        int run = 0;
        for (int i = 0; i < ATH; i++) { int v = sh[t][i]; sh[t][i] = run; run += v; }
        g_cnt[t] = run < CAP ? run : CAP;
    }
    __syncthreads();
    int off[EE];
#pragma unroll
    for (int e = 0; e < EE; e++) off[e] = sh[e][t];
    for (int i = 0; i < EPT; i++) {
        int idx = start + i;
        int e = g_topk_e[idx];
        int pos = off[e]++;
        if (pos < CAP) {
            g_rows[e * CAP + pos] = idx >> 1;      // token index
            g_slot[idx] = e * CAP + pos;
            g_gate[idx] = g_topk_p[idx];
        } else {
            g_slot[idx] = -1;
            g_gate[idx] = 0.f;
        }
    }
}

// ---------------- 3/4) grouped GEMM (128x128x8, f32x2 FMA) -----------------
// MODE 0: H = gelu( gather(x) @ w1[e] + b1[e] )   K=768,  N=3072
// MODE 1: Y = H @ w2[e] + b2[e]                   K=3072, N=768
#define BM 128
#define BN 128
#define BKD 8

template <int MODE>
__global__ __launch_bounds__(256, 2)
void moe_gemm(const float* __restrict__ X,
              const float* __restrict__ W,
              const float* __restrict__ bias) {
    const int KDIM = (MODE == 0) ? DD : HH;
    const int NDIM = (MODE == 0) ? HH : DD;
    const int e = blockIdx.z;
    const int nrows = g_cnt[e];
    const int row0 = blockIdx.y * BM;
    if (row0 >= nrows) return;
    const int col0 = blockIdx.x * BN;
    const float* Wb = W + (size_t)e * KDIM * NDIM;
    const float* bb = bias + (size_t)e * NDIM;

    __shared__ float As[2][BKD][BM];
    __shared__ float Bs[2][BKD][BN];

    const int tid  = threadIdx.x;
    const int arow = tid >> 1;            // 0..127
    const int ak   = (tid & 1) * 4;       // 0 or 4
    const int bk   = tid >> 5;            // 0..7
    const int bc   = (tid & 31) * 4;      // 0..124

    const float* aptr;
    if (MODE == 0) {
        int token = g_rows[e * CAP + row0 + arow] & (NTOK - 1);
        aptr = X + (size_t)token * DD + ak;
    } else {
        aptr = g_Hbuf + (size_t)(e * CAP + row0 + arow) * HH + ak;
    }
    const float* bptr = Wb + (size_t)bk * NDIM + col0 + bc;

    // preload tile 0
    float4 aR = *(const float4*)aptr;
    float4 bR = *(const float4*)bptr;
    As[0][ak + 0][arow] = aR.x; As[0][ak + 1][arow] = aR.y;
    As[0][ak + 2][arow] = aR.z; As[0][ak + 3][arow] = aR.w;
    *(float4*)&Bs[0][bk][bc] = bR;
    __syncthreads();

    uint64_t acc[8][4];
#pragma unroll
    for (int i = 0; i < 8; i++)
#pragma unroll
        for (int j = 0; j < 4; j++) acc[i][j] = 0ull;

    const int tx = tid & 15, ty = tid >> 4;
    const int NT = KDIM / BKD;

    for (int kt = 0; kt < NT; ++kt) {
        const int buf = kt & 1;
        if (kt + 1 < NT) {
            aR = *(const float4*)(aptr + (size_t)(kt + 1) * BKD);
            bR = *(const float4*)(bptr + (size_t)(kt + 1) * BKD * NDIM);
        }
#pragma unroll
        for (int kk = 0; kk < BKD; ++kk) {
            float4 a0 = *(const float4*)&As[buf][kk][ty * 8];
            float4 a1 = *(const float4*)&As[buf][kk][ty * 8 + 4];
            float4 b0 = *(const float4*)&Bs[buf][kk][tx * 8];
            float4 b1 = *(const float4*)&Bs[buf][kk][tx * 8 + 4];
            uint64_t bp0 = pk2(b0.x, b0.y), bp1 = pk2(b0.z, b0.w);
            uint64_t bp2 = pk2(b1.x, b1.y), bp3 = pk2(b1.z, b1.w);
            float av[8] = {a0.x, a0.y, a0.z, a0.w, a1.x, a1.y, a1.z, a1.w};
#pragma unroll
            for (int i = 0; i < 8; i++) {
                uint64_t ad = pk2(av[i], av[i]);
                FMA_F32X2(acc[i][0], ad, bp0);
                FMA_F32X2(acc[i][1], ad, bp1);
                FMA_F32X2(acc[i][2], ad, bp2);
                FMA_F32X2(acc[i][3], ad, bp3);
            }
        }
        if (kt + 1 < NT) {
            const int nb = buf ^ 1;
            As[nb][ak + 0][arow] = aR.x; As[nb][ak + 1][arow] = aR.y;
            As[nb][ak + 2][arow] = aR.z; As[nb][ak + 3][arow] = aR.w;
            *(float4*)&Bs[nb][bk][bc] = bR;
            __syncthreads();
        }
    }

    // epilogue: bias (+gelu for MODE 0), guarded store
    const float s2 = 0.70710678118654752f;
#pragma unroll
    for (int i = 0; i < 8; i++) {
        int gr = row0 + ty * 8 + i;
        if (gr >= nrows) continue;
        float* dst;
        if (MODE == 0)
            dst = g_Hbuf + (size_t)(e * CAP + gr) * HH + col0 + tx * 8;
        else
            dst = g_Ybuf + (size_t)(e * CAP + gr) * DD + col0 + tx * 8;
#pragma unroll
        for (int j = 0; j < 4; j++) {
            float lo, hi;
            unpk2(acc[i][j], lo, hi);
            int c = col0 + tx * 8 + 2 * j;
            float v0 = lo + bb[c];
            float v1 = hi + bb[c + 1];
            if (MODE == 0) {
                v0 = 0.5f * v0 * (1.0f + erff(v0 * s2));
                v1 = 0.5f * v1 * (1.0f + erff(v1 * s2));
            }
            dst[2 * j]     = v0;
            dst[2 * j + 1] = v1;
        }
    }
}

// ---------------- 5) combine: out[t] = g0*Y[slot0] + g1*Y[slot1] -----------
__global__ void combine_kernel(float* __restrict__ out) {
    int t = blockIdx.x;
    int d = threadIdx.x * 4;
    int l0 = g_slot[2 * t], l1 = g_slot[2 * t + 1];
    float g0 = g_gate[2 * t], g1 = g_gate[2 * t + 1];
    float4 r = {0.f, 0.f, 0.f, 0.f};
    if (l0 >= 0) {
        float4 y = *(const float4*)(g_Ybuf + (size_t)l0 * DD + d);
        r.x += g0 * y.x; r.y += g0 * y.y; r.z += g0 * y.z; r.w += g0 * y.w;
    }
    if (l1 >= 0) {
        float4 y = *(const float4*)(g_Ybuf + (size_t)l1 * DD + d);
        r.x += g1 * y.x; r.y += g1 * y.y; r.z += g1 * y.z; r.w += g1 * y.w;
    }
    *(float4*)(out + (size_t)t * DD + d) = r;
}

// ---------------- launch ----------------------------------------------------
extern "C" void kernel_launch(void* const* d_in, const int* in_sizes, int n_in,
                              void* d_out, int out_size) {
    (void)in_sizes; (void)n_in; (void)out_size;
    const float* x  = (const float*)d_in[0];
    const float* Wr = (const float*)d_in[1];
    const float* w1 = (const float*)d_in[2];
    const float* b1 = (const float*)d_in[3];
    const float* w2 = (const float*)d_in[4];
    const float* b2 = (const float*)d_in[5];
    float* out = (float*)d_out;

    router_kernel<<<NTOK / 8, 256>>>(x, Wr);
    assign_kernel<<<1, ATH>>>();
    moe_gemm<0><<<dim3(HH / BN, CAP / BM, EE), 256>>>(x, w1, b1);
    moe_gemm<1><<<dim3(DD / BN, CAP / BM, EE), 256>>>(x, w2, b2);
    combine_kernel<<<NTOK, DD / 4>>>(out);
}

// round 7
// speedup vs baseline: 1.8398x; 1.8398x over previous
#include <cuda_runtime.h>
#include <cuda_bf16.h>
#include <math.h>
#include <stdint.h>

// Problem constants
#define BZ 4
#define SZ 2048
#define DD 768
#define HH 3072
#define EE 8
#define NTOK (BZ*SZ)          // 8192
#define NENT (NTOK*2)         // 16384
#define CAP  1536
#define ROWS_MAX (EE*CAP)     // 12288

// ---------------- device scratch (same footprint as passing R2) -------------
__device__ int   g_topk_e[NENT];
__device__ float g_topk_p[NENT];
__device__ int   g_rows[ROWS_MAX];
__device__ int   g_cnt[EE];
__device__ int   g_slot[NENT];
__device__ float g_gate[NENT];
__device__ float g_Hbuf[(size_t)ROWS_MAX * HH];   // 151 MB
__device__ float g_Ybuf[(size_t)ROWS_MAX * DD];   // 37.7 MB

// ---------------- PTX helpers (plain sm_100 features only) ------------------
__device__ __forceinline__ uint32_t smem_u32(const void* p) {
    uint32_t a;
    asm("{ .reg .u64 t; cvta.to.shared.u64 t, %1; cvt.u32.u64 %0, t; }" : "=r"(a) : "l"(p));
    return a;
}
__device__ __forceinline__ void ldsm4(uint32_t& r0, uint32_t& r1, uint32_t& r2, uint32_t& r3,
                                      uint32_t addr) {
    asm volatile("ldmatrix.sync.aligned.m8n8.x4.shared.b16 {%0,%1,%2,%3}, [%4];"
                 : "=r"(r0), "=r"(r1), "=r"(r2), "=r"(r3) : "r"(addr));
}
__device__ __forceinline__ void ldsm4t(uint32_t& r0, uint32_t& r1, uint32_t& r2, uint32_t& r3,
                                       uint32_t addr) {
    asm volatile("ldmatrix.sync.aligned.m8n8.x4.trans.shared.b16 {%0,%1,%2,%3}, [%4];"
                 : "=r"(r0), "=r"(r1), "=r"(r2), "=r"(r3) : "r"(addr));
}
__device__ __forceinline__ void mma16816(float& c0, float& c1, float& c2, float& c3,
                                         uint32_t a0, uint32_t a1, uint32_t a2, uint32_t a3,
                                         uint32_t b0, uint32_t b1) {
    asm volatile("mma.sync.aligned.m16n8k16.row.col.f32.bf16.bf16.f32 "
                 "{%0,%1,%2,%3}, {%4,%5,%6,%7}, {%8,%9}, {%0,%1,%2,%3};"
                 : "+f"(c0), "+f"(c1), "+f"(c2), "+f"(c3)
                 : "r"(a0), "r"(a1), "r"(a2), "r"(a3), "r"(b0), "r"(b1));
}
// split 2 floats -> packed bf16x2 hi and bf16x2 lo
__device__ __forceinline__ void split2(float f0, float f1, uint32_t& hi, uint32_t& lo) {
    __nv_bfloat16 h0 = __float2bfloat16(f0), h1 = __float2bfloat16(f1);
    __nv_bfloat16 l0 = __float2bfloat16(f0 - __bfloat162float(h0));
    __nv_bfloat16 l1 = __float2bfloat16(f1 - __bfloat162float(h1));
    hi = (uint32_t)*(unsigned short*)&h0 | ((uint32_t)*(unsigned short*)&h1 << 16);
    lo = (uint32_t)*(unsigned short*)&l0 | ((uint32_t)*(unsigned short*)&l1 << 16);
}

// ---------------- router (identical to passing R2) ---------------------------
__global__ void router_kernel(const float* __restrict__ x,
                              const float* __restrict__ Wr) {
    int warp = threadIdx.x >> 5;
    int lane = threadIdx.x & 31;
    int t = blockIdx.x * 8 + warp;
    if (t >= NTOK) return;
    const float* xr = x + (size_t)t * DD;
    float acc[EE];
#pragma unroll
    for (int e = 0; e < EE; e++) acc[e] = 0.f;
    for (int i = lane; i < DD; i += 32) {
        float xv = xr[i];
        const float4* wr4 = reinterpret_cast<const float4*>(Wr + i * EE);
        float4 w0 = wr4[0], w1 = wr4[1];
        acc[0] += xv * w0.x; acc[1] += xv * w0.y;
        acc[2] += xv * w0.z; acc[3] += xv * w0.w;
        acc[4] += xv * w1.x; acc[5] += xv * w1.y;
        acc[6] += xv * w1.z; acc[7] += xv * w1.w;
    }
#pragma unroll
    for (int e = 0; e < EE; e++)
#pragma unroll
        for (int o = 16; o > 0; o >>= 1)
            acc[e] += __shfl_xor_sync(0xffffffffu, acc[e], o);
    if (lane == 0) {
        float m = acc[0];
#pragma unroll
        for (int e = 1; e < EE; e++) m = fmaxf(m, acc[e]);
        float p[EE]; float s = 0.f;
#pragma unroll
        for (int e = 0; e < EE; e++) { p[e] = expf(acc[e] - m); s += p[e]; }
        float inv = 1.f / s;
#pragma unroll
        for (int e = 0; e < EE; e++) p[e] *= inv;
        int i0 = 0;
#pragma unroll
        for (int e = 1; e < EE; e++) if (p[e] > p[i0]) i0 = e;
        int i1 = -1;
#pragma unroll
        for (int e = 0; e < EE; e++) {
            if (e == i0) continue;
            if (i1 < 0 || p[e] > p[i1]) i1 = e;
        }
        float ps = 1.f / (p[i0] + p[i1]);
        g_topk_e[2 * t + 0] = i0; g_topk_p[2 * t + 0] = p[i0] * ps;
        g_topk_e[2 * t + 1] = i1; g_topk_p[2 * t + 1] = p[i1] * ps;
    }
}

// ---------------- capacity assignment (exact flat-order, static indexing) ----
#define ATH 512
#define EPT (NENT / ATH)
__global__ void assign_kernel() {
    __shared__ int sh[EE][ATH];
    int t = threadIdx.x;
    int loc[EE];
#pragma unroll
    for (int e = 0; e < EE; e++) loc[e] = 0;
    int start = t * EPT;
    for (int i = 0; i < EPT; i++) {
        int ev = g_topk_e[start + i];
#pragma unroll
        for (int e = 0; e < EE; e++) loc[e] += (ev == e);
    }
#pragma unroll
    for (int e = 0; e < EE; e++) sh[e][t] = loc[e];
    __syncthreads();
    if (t < EE) {
        int run = 0;
        for (int i = 0; i < ATH; i++) { int v = sh[t][i]; sh[t][i] = run; run += v; }
        g_cnt[t] = run < CAP ? run : CAP;
    }
    __syncthreads();
    int off[EE];
#pragma unroll
    for (int e = 0; e < EE; e++) off[e] = sh[e][t];
    for (int i = 0; i < EPT; i++) {
        int idx = start + i;
        int ev = g_topk_e[idx];
        int pos = 0;
#pragma unroll
        for (int e = 0; e < EE; e++) {
            if (ev == e) { pos = off[e]; off[e] = pos + 1; }
        }
        if (pos < CAP) {
            g_rows[ev * CAP + pos] = idx >> 1;
            g_slot[idx] = ev * CAP + pos;
            g_gate[idx] = g_topk_p[idx];
        } else {
            g_slot[idx] = -1;
            g_gate[idx] = 0.f;
        }
    }
}

// ---------------- HMMA grouped GEMM, on-the-fly bf16 split -------------------
// CTA tile 128x128, K-tile 32, 512 threads (16 warps, warp tile 32x32).
// Two-buffer register-staged pipeline (one barrier per K-tile, as in R2).
// A smem plane: [128 m][32 k] bf16, row stride 80 B (hi & lo planes).
// B smem plane: [32 k][128 n] bf16, row stride 272 B (hi & lo planes);
//   B fragments via ldmatrix.x4.trans (weights read in NATIVE [K][N] layout).
// MODE 0: H = gelu(gather(x) @ w1 + b1), K=768,  N=3072 -> g_Hbuf fp32
// MODE 1: Y = H @ w2 + b2,               K=3072, N=768  -> g_Ybuf fp32
#define AROW 80
#define BROW 272
#define APL  (128 * AROW)              // 10240 B
#define BPL  (32 * BROW)               // 8704 B
#define BUFB (2 * APL + 2 * BPL)       // 37888 B per buffer
#define GEMM_SMEM (2 * BUFB)           // 75776 B

template <int MODE>
__global__ void __launch_bounds__(512) moe_gemm(const float* __restrict__ X,
                                                const float* __restrict__ W,
                                                const float* __restrict__ bias) {
    constexpr int KDIM = (MODE == 0) ? DD : HH;
    constexpr int NDIM = (MODE == 0) ? HH : DD;
    constexpr int NT = KDIM / 32;
    extern __shared__ char smem[];

    const int e = blockIdx.z;
    const int nrows = g_cnt[e];
    const int row0 = blockIdx.y * 128;
    if (row0 >= nrows) return;
    const int col0 = blockIdx.x * 128;
    const int tid = threadIdx.x;
    const int l = tid & 31, wid = tid >> 5;
    const int wm = wid & 3, wn = wid >> 2;        // 4x4 warps, each 32m x 32n
    const uint32_t sb0 = smem_u32(smem);

    // ---- loader indices: A 1024 16B-chunks, B 1024 16B-chunks, 2 each -----
    const int am = tid >> 3, akc = tid & 7;       // A chunk0: row am, 16B col akc
    const int bk = tid >> 5, bnc = tid & 31;      // B chunk0: k bk, 16B col bnc
    // A sources (fp32)
    const float *pA0, *pA1;
    if (MODE == 0) {
        int t0 = g_rows[e * CAP + row0 + am] & (NTOK - 1);
        int t1 = g_rows[e * CAP + row0 + am + 64] & (NTOK - 1);
        pA0 = X + (size_t)t0 * DD + akc * 4;
        pA1 = X + (size_t)t1 * DD + akc * 4;
    } else {
        pA0 = g_Hbuf + (size_t)(e * CAP + row0 + am) * HH + akc * 4;
        pA1 = g_Hbuf + (size_t)(e * CAP + row0 + am + 64) * HH + akc * 4;
    }
    // B source (fp32, native [K][N] layout: row k stride NDIM)
    const float* pB0 = W + (size_t)e * KDIM * NDIM + (size_t)bk * NDIM + col0 + bnc * 4;
    const float* pB1 = pB0 + (size_t)16 * NDIM;
    // smem store offsets
    const uint32_t sA = (uint32_t)(am * AROW + akc * 8);          // 4 bf16 = 8 B
    const uint32_t sB = (uint32_t)(bk * BROW + bnc * 8);

    // ---- fragment lane offsets ---------------------------------------------
    const uint32_t offA = (uint32_t)((wm * 32 + (l & 15)) * AROW + ((l >> 4) & 1) * 16);
    const uint32_t offBt = (uint32_t)((((l & 7) + ((l >> 3) & 1) * 8)) * BROW
                                      + (l >> 4) * 16 + (wn * 32) * 2);

    float acc[2][4][4];
#pragma unroll
    for (int mi = 0; mi < 2; mi++)
#pragma unroll
        for (int nj = 0; nj < 4; nj++)
#pragma unroll
            for (int q = 0; q < 4; q++) acc[mi][nj][q] = 0.f;

    // ---- prefetch tile 0 ----------------------------------------------------
    float4 a0 = *(const float4*)pA0;
    float4 a1 = *(const float4*)pA1;
    float4 b0 = *(const float4*)pB0;
    float4 b1 = *(const float4*)pB1;

    for (int kt = 0; kt < NT; kt++) {
        const uint32_t sbuf = sb0 + (kt & 1) * BUFB;
        // split + store current registers into buffer (kt&1)
        {
            uint32_t h0, l0v, h1, l1v;
            split2(a0.x, a0.y, h0, l0v); split2(a0.z, a0.w, h1, l1v);
            *(uint2*)(smem + (sbuf - sb0) + sA)       = make_uint2(h0, h1);
            *(uint2*)(smem + (sbuf - sb0) + APL + sA) = make_uint2(l0v, l1v);
            split2(a1.x, a1.y, h0, l0v); split2(a1.z, a1.w, h1, l1v);
            *(uint2*)(smem + (sbuf - sb0) + sA + 64 * AROW)       = make_uint2(h0, h1);
            *(uint2*)(smem + (sbuf - sb0) + APL + sA + 64 * AROW) = make_uint2(l0v, l1v);
            split2(b0.x, b0.y, h0, l0v); split2(b0.z, b0.w, h1, l1v);
            *(uint2*)(smem + (sbuf - sb0) + 2 * APL + sB)       = make_uint2(h0, h1);
            *(uint2*)(smem + (sbuf - sb0) + 2 * APL + BPL + sB) = make_uint2(l0v, l1v);
            split2(b1.x, b1.y, h0, l0v); split2(b1.z, b1.w, h1, l1v);
            *(uint2*)(smem + (sbuf - sb0) + 2 * APL + sB + 16 * BROW)       = make_uint2(h0, h1);
            *(uint2*)(smem + (sbuf - sb0) + 2 * APL + BPL + sB + 16 * BROW) = make_uint2(l0v, l1v);
        }
        __syncthreads();
        // prefetch next tile into registers (hidden under compute)
        if (kt + 1 < NT) {
            a0 = *(const float4*)(pA0 + (size_t)(kt + 1) * 32);
            a1 = *(const float4*)(pA1 + (size_t)(kt + 1) * 32);
            b0 = *(const float4*)(pB0 + (size_t)(kt + 1) * 32 * NDIM);
            b1 = *(const float4*)(pB1 + (size_t)(kt + 1) * 32 * NDIM);
        }
        // compute on buffer (kt&1)
        const uint32_t sbA = sbuf;
        const uint32_t sbB = sbuf + 2 * APL;
#pragma unroll
        for (int k16 = 0; k16 < 2; k16++) {
            const uint32_t kbA = k16 * 32;          // 16 bf16 = 32 B
            const uint32_t kbB = k16 * 16 * BROW;   // 16 k-rows
            uint32_t ah0, ah1, ah2, ah3, ag0, ag1, ag2, ag3;
            uint32_t al0, al1, al2, al3, am0, am1, am2, am3;
            ldsm4(ah0, ah1, ah2, ah3, sbA + offA + kbA);                 // m16 tile 0 hi
            ldsm4(ag0, ag1, ag2, ag3, sbA + offA + 16 * AROW + kbA);     // m16 tile 1 hi
            ldsm4(al0, al1, al2, al3, sbA + APL + offA + kbA);           // lo
            ldsm4(am0, am1, am2, am3, sbA + APL + offA + 16 * AROW + kbA);
#pragma unroll
            for (int j = 0; j < 2; j++) {           // two n16 groups -> 4 n8 tiles
                uint32_t bh0, bh1, bh2, bh3, bl0, bl1, bl2, bl3;
                ldsm4t(bh0, bh1, bh2, bh3, sbB + offBt + kbB + j * 32);
                ldsm4t(bl0, bl1, bl2, bl3, sbB + BPL + offBt + kbB + j * 32);
                // n8 tile (2j): regs {bh0,bh1}; n8 tile (2j+1): {bh2,bh3}
                mma16816(acc[0][2*j][0], acc[0][2*j][1], acc[0][2*j][2], acc[0][2*j][3],
                         ah0, ah1, ah2, ah3, bh0, bh1);
                mma16816(acc[0][2*j][0], acc[0][2*j][1], acc[0][2*j][2], acc[0][2*j][3],
                         ah0, ah1, ah2, ah3, bl0, bl1);
                mma16816(acc[0][2*j][0], acc[0][2*j][1], acc[0][2*j][2], acc[0][2*j][3],
                         al0, al1, al2, al3, bh0, bh1);
                mma16816(acc[0][2*j+1][0], acc[0][2*j+1][1], acc[0][2*j+1][2], acc[0][2*j+1][3],
                         ah0, ah1, ah2, ah3, bh2, bh3);
                mma16816(acc[0][2*j+1][0], acc[0][2*j+1][1], acc[0][2*j+1][2], acc[0][2*j+1][3],
                         ah0, ah1, ah2, ah3, bl2, bl3);
                mma16816(acc[0][2*j+1][0], acc[0][2*j+1][1], acc[0][2*j+1][2], acc[0][2*j+1][3],
                         al0, al1, al2, al3, bh2, bh3);
                mma16816(acc[1][2*j][0], acc[1][2*j][1], acc[1][2*j][2], acc[1][2*j][3],
                         ag0, ag1, ag2, ag3, bh0, bh1);
                mma16816(acc[1][2*j][0], acc[1][2*j][1], acc[1][2*j][2], acc[1][2*j][3],
                         ag0, ag1, ag2, ag3, bl0, bl1);
                mma16816(acc[1][2*j][0], acc[1][2*j][1], acc[1][2*j][2], acc[1][2*j][3],
                         am0, am1, am2, am3, bh0, bh1);
                mma16816(acc[1][2*j+1][0], acc[1][2*j+1][1], acc[1][2*j+1][2], acc[1][2*j+1][3],
                         ag0, ag1, ag2, ag3, bh2, bh3);
                mma16816(acc[1][2*j+1][0], acc[1][2*j+1][1], acc[1][2*j+1][2], acc[1][2*j+1][3],
                         ag0, ag1, ag2, ag3, bl2, bl3);
                mma16816(acc[1][2*j+1][0], acc[1][2*j+1][1], acc[1][2*j+1][2], acc[1][2*j+1][3],
                         am0, am1, am2, am3, bh2, bh3);
            }
        }
        __syncthreads();   // buffer consumed by all warps before it is refilled
    }

    // ---- epilogue -----------------------------------------------------------
    const float s2 = 0.70710678118654752f;
    const float* bb = bias + (size_t)e * NDIM;
#pragma unroll
    for (int mi = 0; mi < 2; mi++) {
#pragma unroll
        for (int h = 0; h < 2; h++) {
            int row = row0 + wm * 32 + mi * 16 + (l >> 2) + h * 8;
            if (row >= nrows) continue;
#pragma unroll
            for (int nj = 0; nj < 4; nj++) {
                int coln = col0 + wn * 32 + nj * 8 + (l & 3) * 2;
                float v0 = acc[mi][nj][h * 2 + 0] + bb[coln];
                float v1 = acc[mi][nj][h * 2 + 1] + bb[coln + 1];
                if (MODE == 0) {
                    v0 = 0.5f * v0 * (1.0f + erff(v0 * s2));
                    v1 = 0.5f * v1 * (1.0f + erff(v1 * s2));
                    size_t idx = (size_t)(e * CAP + row) * HH + coln;
                    float2 o2 = {v0, v1};
                    *reinterpret_cast<float2*>(&g_Hbuf[idx]) = o2;
                } else {
                    size_t idx = (size_t)(e * CAP + row) * DD + coln;
                    float2 o2 = {v0, v1};
                    *reinterpret_cast<float2*>(&g_Ybuf[idx]) = o2;
                }
            }
        }
    }
}

// ---------------- combine ----------------------------------------------------
__global__ void combine_kernel(float* __restrict__ out) {
    int t = blockIdx.x;
    int d = threadIdx.x * 4;
    int l0 = g_slot[2 * t], l1 = g_slot[2 * t + 1];
    float g0 = g_gate[2 * t], g1 = g_gate[2 * t + 1];
    float4 r = {0.f, 0.f, 0.f, 0.f};
    if (l0 >= 0) {
        float4 y = *(const float4*)(g_Ybuf + (size_t)l0 * DD + d);
        r.x += g0 * y.x; r.y += g0 * y.y; r.z += g0 * y.z; r.w += g0 * y.w;
    }
    if (l1 >= 0) {
        float4 y = *(const float4*)(g_Ybuf + (size_t)l1 * DD + d);
        r.x += g1 * y.x; r.y += g1 * y.y; r.z += g1 * y.z; r.w += g1 * y.w;
    }
    *(float4*)(out + (size_t)t * DD + d) = r;
}

// ---------------- launch -----------------------------------------------------
extern "C" void kernel_launch(void* const* d_in, const int* in_sizes, int n_in,
                              void* d_out, int out_size) {
    (void)in_sizes; (void)n_in; (void)out_size;
    const float* x  = (const float*)d_in[0];
    const float* Wr = (const float*)d_in[1];
    const float* w1 = (const float*)d_in[2];
    const float* b1 = (const float*)d_in[3];
    const float* w2 = (const float*)d_in[4];
    const float* b2 = (const float*)d_in[5];
    float* out = (float*)d_out;

    cudaFuncSetAttribute(moe_gemm<0>, cudaFuncAttributeMaxDynamicSharedMemorySize, GEMM_SMEM);
    cudaFuncSetAttribute(moe_gemm<1>, cudaFuncAttributeMaxDynamicSharedMemorySize, GEMM_SMEM);

    router_kernel<<<NTOK / 8, 256>>>(x, Wr);
    assign_kernel<<<1, ATH>>>();
    moe_gemm<0><<<dim3(HH / 128, CAP / 128, EE), 512, GEMM_SMEM>>>(x, w1, b1);
    moe_gemm<1><<<dim3(DD / 128, CAP / 128, EE), 512, GEMM_SMEM>>>(nullptr, w2, b2);
    combine_kernel<<<NTOK, DD / 4>>>(out);
}

// round 8
// speedup vs baseline: 2.1361x; 1.1610x over previous
#include <cuda_runtime.h>
#include <cuda_bf16.h>
#include <math.h>
#include <stdint.h>

// Problem constants
#define BZ 4
#define SZ 2048
#define DD 768
#define HH 3072
#define EE 8
#define NTOK (BZ*SZ)          // 8192
#define NENT (NTOK*2)         // 16384
#define CAP  1536
#define ROWS_MAX (EE*CAP)     // 12288

// ---------------- device scratch (same footprint as passing R7) -------------
__device__ int   g_topk_e[NENT];
__device__ float g_topk_p[NENT];
__device__ int   g_rows[ROWS_MAX];
__device__ int   g_cnt[EE];
__device__ int   g_slot[NENT];
__device__ float g_gate[NENT];
__device__ float g_Hbuf[(size_t)ROWS_MAX * HH];   // 151 MB
__device__ float g_Ybuf[(size_t)ROWS_MAX * DD];   // 37.7 MB

// ---------------- PTX helpers (plain sm_100 features only) ------------------
__device__ __forceinline__ uint32_t smem_u32(const void* p) {
    uint32_t a;
    asm("{ .reg .u64 t; cvta.to.shared.u64 t, %1; cvt.u32.u64 %0, t; }" : "=r"(a) : "l"(p));
    return a;
}
__device__ __forceinline__ void ldsm4(uint32_t& r0, uint32_t& r1, uint32_t& r2, uint32_t& r3,
                                      uint32_t addr) {
    asm volatile("ldmatrix.sync.aligned.m8n8.x4.shared.b16 {%0,%1,%2,%3}, [%4];"
                 : "=r"(r0), "=r"(r1), "=r"(r2), "=r"(r3) : "r"(addr));
}
__device__ __forceinline__ void ldsm4t(uint32_t& r0, uint32_t& r1, uint32_t& r2, uint32_t& r3,
                                       uint32_t addr) {
    asm volatile("ldmatrix.sync.aligned.m8n8.x4.trans.shared.b16 {%0,%1,%2,%3}, [%4];"
                 : "=r"(r0), "=r"(r1), "=r"(r2), "=r"(r3) : "r"(addr));
}
__device__ __forceinline__ void mma16816(float& c0, float& c1, float& c2, float& c3,
                                         uint32_t a0, uint32_t a1, uint32_t a2, uint32_t a3,
                                         uint32_t b0, uint32_t b1) {
    asm volatile("mma.sync.aligned.m16n8k16.row.col.f32.bf16.bf16.f32 "
                 "{%0,%1,%2,%3}, {%4,%5,%6,%7}, {%8,%9}, {%0,%1,%2,%3};"
                 : "+f"(c0), "+f"(c1), "+f"(c2), "+f"(c3)
                 : "r"(a0), "r"(a1), "r"(a2), "r"(a3), "r"(b0), "r"(b1));
}
// split 2 floats -> packed bf16x2 hi and bf16x2 lo
__device__ __forceinline__ void split2(float f0, float f1, uint32_t& hi, uint32_t& lo) {
    __nv_bfloat16 h0 = __float2bfloat16(f0), h1 = __float2bfloat16(f1);
    __nv_bfloat16 l0 = __float2bfloat16(f0 - __bfloat162float(h0));
    __nv_bfloat16 l1 = __float2bfloat16(f1 - __bfloat162float(h1));
    hi = (uint32_t)*(unsigned short*)&h0 | ((uint32_t)*(unsigned short*)&h1 << 16);
    lo = (uint32_t)*(unsigned short*)&l0 | ((uint32_t)*(unsigned short*)&l1 << 16);
}

// ---------------- router -----------------------------------------------------
__global__ void router_kernel(const float* __restrict__ x,
                              const float* __restrict__ Wr) {
    int warp = threadIdx.x >> 5;
    int lane = threadIdx.x & 31;
    int t = blockIdx.x * 8 + warp;
    if (t >= NTOK) return;
    const float* xr = x + (size_t)t * DD;
    float acc[EE];
#pragma unroll
    for (int e = 0; e < EE; e++) acc[e] = 0.f;
    for (int i = lane; i < DD; i += 32) {
        float xv = xr[i];
        const float4* wr4 = reinterpret_cast<const float4*>(Wr + i * EE);
        float4 w0 = wr4[0], w1 = wr4[1];
        acc[0] += xv * w0.x; acc[1] += xv * w0.y;
        acc[2] += xv * w0.z; acc[3] += xv * w0.w;
        acc[4] += xv * w1.x; acc[5] += xv * w1.y;
        acc[6] += xv * w1.z; acc[7] += xv * w1.w;
    }
#pragma unroll
    for (int e = 0; e < EE; e++)
#pragma unroll
        for (int o = 16; o > 0; o >>= 1)
            acc[e] += __shfl_xor_sync(0xffffffffu, acc[e], o);
    if (lane == 0) {
        float m = acc[0];
#pragma unroll
        for (int e = 1; e < EE; e++) m = fmaxf(m, acc[e]);
        float p[EE]; float s = 0.f;
#pragma unroll
        for (int e = 0; e < EE; e++) { p[e] = expf(acc[e] - m); s += p[e]; }
        float inv = 1.f / s;
#pragma unroll
        for (int e = 0; e < EE; e++) p[e] *= inv;
        int i0 = 0;
#pragma unroll
        for (int e = 1; e < EE; e++) if (p[e] > p[i0]) i0 = e;
        int i1 = -1;
#pragma unroll
        for (int e = 0; e < EE; e++) {
            if (e == i0) continue;
            if (i1 < 0 || p[e] > p[i1]) i1 = e;
        }
        float ps = 1.f / (p[i0] + p[i1]);
        g_topk_e[2 * t + 0] = i0; g_topk_p[2 * t + 0] = p[i0] * ps;
        g_topk_e[2 * t + 1] = i1; g_topk_p[2 * t + 1] = p[i1] * ps;
    }
}

// ---------------- capacity assignment (exact flat-order, static indexing) ----
#define ATH 512
#define EPT (NENT / ATH)
__global__ void assign_kernel() {
    __shared__ int sh[EE][ATH];
    int t = threadIdx.x;
    int loc[EE];
#pragma unroll
    for (int e = 0; e < EE; e++) loc[e] = 0;
    int start = t * EPT;
    for (int i = 0; i < EPT; i++) {
        int ev = g_topk_e[start + i];
#pragma unroll
        for (int e = 0; e < EE; e++) loc[e] += (ev == e);
    }
#pragma unroll
    for (int e = 0; e < EE; e++) sh[e][t] = loc[e];
    __syncthreads();
    if (t < EE) {
        int run = 0;
        for (int i = 0; i < ATH; i++) { int v = sh[t][i]; sh[t][i] = run; run += v; }
        g_cnt[t] = run < CAP ? run : CAP;
    }
    __syncthreads();
    int off[EE];
#pragma unroll
    for (int e = 0; e < EE; e++) off[e] = sh[e][t];
    for (int i = 0; i < EPT; i++) {
        int idx = start + i;
        int ev = g_topk_e[idx];
        int pos = 0;
#pragma unroll
        for (int e = 0; e < EE; e++) {
            if (ev == e) { pos = off[e]; off[e] = pos + 1; }
        }
        if (pos < CAP) {
            g_rows[ev * CAP + pos] = idx >> 1;
            g_slot[idx] = ev * CAP + pos;
            g_gate[idx] = g_topk_p[idx];
        } else {
            g_slot[idx] = -1;
            g_gate[idx] = 0.f;
        }
    }
}

// ---------------- HMMA grouped GEMM, 128x256 tile, on-the-fly split ----------
// 512 threads (16 warps, 4x4), warp tile 32x64, K-tile 32.
// Double-buffered, ONE barrier per K-tile (store -> prefetch -> SYNC -> compute).
// A smem: [128 m][32 k] bf16, row 80 B (hi & lo planes).
// B smem: [32 k][256 n] bf16, row 528 B (hi & lo planes), ldmatrix.trans.
// MODE 0: H = gelu(gather(x) @ w1 + b1), K=768,  N=3072 -> g_Hbuf fp32
// MODE 1: Y = H @ w2 + b2,               K=3072, N=768  -> g_Ybuf fp32
#define AROW 80
#define BROW 528
#define APL  (128 * AROW)              // 10240 B
#define BPL  (32 * BROW)               // 16896 B
#define BUFB (2 * APL + 2 * BPL)       // 54272 B per buffer
#define GEMM_SMEM (2 * BUFB)           // 108544 B

template <int MODE>
__global__ void __launch_bounds__(512) moe_gemm(const float* __restrict__ X,
                                                const float* __restrict__ W,
                                                const float* __restrict__ bias) {
    constexpr int KDIM = (MODE == 0) ? DD : HH;
    constexpr int NDIM = (MODE == 0) ? HH : DD;
    constexpr int NT = KDIM / 32;
    extern __shared__ char smem[];

    const int e = blockIdx.z;
    const int nrows = g_cnt[e];
    const int row0 = blockIdx.y * 128;
    if (row0 >= nrows) return;
    const int col0 = blockIdx.x * 256;
    const int tid = threadIdx.x;
    const int l = tid & 31, wid = tid >> 5;
    const int wm = wid & 3, wn = wid >> 2;        // 4x4 warps: 32m x 64n each
    const uint32_t sb0 = smem_u32(smem);

    // ---- loader indices ----------------------------------------------------
    // A: 1024 16B chunks (2/thread): rows am, am+64, 16B col akc
    const int am = tid >> 3, akc = tid & 7;
    // B: 2048 16B chunks (4/thread): row (tid>>6)+8t, 16B col tid&63
    const int bk = tid >> 6, bnc = tid & 63;
    const float *pA0, *pA1;
    if (MODE == 0) {
        int t0 = g_rows[e * CAP + row0 + am] & (NTOK - 1);
        int t1 = g_rows[e * CAP + row0 + am + 64] & (NTOK - 1);
        pA0 = X + (size_t)t0 * DD + akc * 4;
        pA1 = X + (size_t)t1 * DD + akc * 4;
    } else {
        pA0 = g_Hbuf + (size_t)(e * CAP + row0 + am) * HH + akc * 4;
        pA1 = g_Hbuf + (size_t)(e * CAP + row0 + am + 64) * HH + akc * 4;
    }
    const float* pB = W + (size_t)e * KDIM * NDIM + (size_t)bk * NDIM + col0 + bnc * 4;
    const uint32_t sA = (uint32_t)(am * AROW + akc * 8);
    const uint32_t sB = (uint32_t)(bk * BROW + bnc * 8);

    // ---- fragment lane offsets ---------------------------------------------
    const uint32_t offA = (uint32_t)((wm * 32 + (l & 15)) * AROW + ((l >> 4) & 1) * 16);
    const uint32_t offBt = (uint32_t)((((l & 7) + ((l >> 3) & 1) * 8)) * BROW
                                      + (l >> 4) * 16 + wn * 128);   // wn*64 cols * 2B

    float acc[2][8][4];
#pragma unroll
    for (int mi = 0; mi < 2; mi++)
#pragma unroll
        for (int nj = 0; nj < 8; nj++)
#pragma unroll
            for (int q = 0; q < 4; q++) acc[mi][nj][q] = 0.f;

    // ---- prefetch tile 0 ----------------------------------------------------
    float4 aR0 = *(const float4*)pA0;
    float4 aR1 = *(const float4*)pA1;
    float4 bR0 = *(const float4*)(pB);
    float4 bR1 = *(const float4*)(pB + (size_t)8 * NDIM);
    float4 bR2 = *(const float4*)(pB + (size_t)16 * NDIM);
    float4 bR3 = *(const float4*)(pB + (size_t)24 * NDIM);

    for (int kt = 0; kt < NT; kt++) {
        char* buf = smem + (kt & 1) * BUFB;
        // ---- split + store current tile ------------------------------------
        {
            uint32_t h0, v0, h1, v1;
            split2(aR0.x, aR0.y, h0, v0); split2(aR0.z, aR0.w, h1, v1);
            *(uint2*)(buf + sA)       = make_uint2(h0, h1);
            *(uint2*)(buf + APL + sA) = make_uint2(v0, v1);
            split2(aR1.x, aR1.y, h0, v0); split2(aR1.z, aR1.w, h1, v1);
            *(uint2*)(buf + sA + 64 * AROW)       = make_uint2(h0, h1);
            *(uint2*)(buf + APL + sA + 64 * AROW) = make_uint2(v0, v1);
            split2(bR0.x, bR0.y, h0, v0); split2(bR0.z, bR0.w, h1, v1);
            *(uint2*)(buf + 2 * APL + sB)       = make_uint2(h0, h1);
            *(uint2*)(buf + 2 * APL + BPL + sB) = make_uint2(v0, v1);
            split2(bR1.x, bR1.y, h0, v0); split2(bR1.z, bR1.w, h1, v1);
            *(uint2*)(buf + 2 * APL + sB + 8 * BROW)       = make_uint2(h0, h1);
            *(uint2*)(buf + 2 * APL + BPL + sB + 8 * BROW) = make_uint2(v0, v1);
            split2(bR2.x, bR2.y, h0, v0); split2(bR2.z, bR2.w, h1, v1);
            *(uint2*)(buf + 2 * APL + sB + 16 * BROW)       = make_uint2(h0, h1);
            *(uint2*)(buf + 2 * APL + BPL + sB + 16 * BROW) = make_uint2(v0, v1);
            split2(bR3.x, bR3.y, h0, v0); split2(bR3.z, bR3.w, h1, v1);
            *(uint2*)(buf + 2 * APL + sB + 24 * BROW)       = make_uint2(h0, h1);
            *(uint2*)(buf + 2 * APL + BPL + sB + 24 * BROW) = make_uint2(v0, v1);
        }
        // ---- prefetch next tile (loads fly during the barrier) -------------
        if (kt + 1 < NT) {
            size_t ka = (size_t)(kt + 1) * 32;
            size_t kb = (size_t)(kt + 1) * 32 * NDIM;
            aR0 = *(const float4*)(pA0 + ka);
            aR1 = *(const float4*)(pA1 + ka);
            bR0 = *(const float4*)(pB + kb);
            bR1 = *(const float4*)(pB + kb + (size_t)8 * NDIM);
            bR2 = *(const float4*)(pB + kb + (size_t)16 * NDIM);
            bR3 = *(const float4*)(pB + kb + (size_t)24 * NDIM);
        }
        __syncthreads();   // single barrier per K-tile (double-buffer safe)
        // ---- compute on this buffer ----------------------------------------
        const uint32_t sbA = sb0 + (kt & 1) * BUFB;
        const uint32_t sbB = sbA + 2 * APL;
#pragma unroll
        for (int k16 = 0; k16 < 2; k16++) {
            const uint32_t kbA = k16 * 32;
            const uint32_t kbB = k16 * 16 * BROW;
            uint32_t ah0, ah1, ah2, ah3, ag0, ag1, ag2, ag3;
            uint32_t al0, al1, al2, al3, am0, am1, am2, am3;
            ldsm4(ah0, ah1, ah2, ah3, sbA + offA + kbA);
            ldsm4(ag0, ag1, ag2, ag3, sbA + offA + 16 * AROW + kbA);
            ldsm4(al0, al1, al2, al3, sbA + APL + offA + kbA);
            ldsm4(am0, am1, am2, am3, sbA + APL + offA + 16 * AROW + kbA);
#pragma unroll
            for (int j = 0; j < 4; j++) {          // four n16 groups
                uint32_t bh0, bh1, bh2, bh3, bl0, bl1, bl2, bl3;
                ldsm4t(bh0, bh1, bh2, bh3, sbB + offBt + kbB + j * 32);
                ldsm4t(bl0, bl1, bl2, bl3, sbB + BPL + offBt + kbB + j * 32);
                mma16816(acc[0][2*j][0], acc[0][2*j][1], acc[0][2*j][2], acc[0][2*j][3],
                         ah0, ah1, ah2, ah3, bh0, bh1);
                mma16816(acc[0][2*j][0], acc[0][2*j][1], acc[0][2*j][2], acc[0][2*j][3],
                         ah0, ah1, ah2, ah3, bl0, bl1);
                mma16816(acc[0][2*j][0], acc[0][2*j][1], acc[0][2*j][2], acc[0][2*j][3],
                         al0, al1, al2, al3, bh0, bh1);
                mma16816(acc[0][2*j+1][0], acc[0][2*j+1][1], acc[0][2*j+1][2], acc[0][2*j+1][3],
                         ah0, ah1, ah2, ah3, bh2, bh3);
                mma16816(acc[0][2*j+1][0], acc[0][2*j+1][1], acc[0][2*j+1][2], acc[0][2*j+1][3],
                         ah0, ah1, ah2, ah3, bl2, bl3);
                mma16816(acc[0][2*j+1][0], acc[0][2*j+1][1], acc[0][2*j+1][2], acc[0][2*j+1][3],
                         al0, al1, al2, al3, bh2, bh3);
                mma16816(acc[1][2*j][0], acc[1][2*j][1], acc[1][2*j][2], acc[1][2*j][3],
                         ag0, ag1, ag2, ag3, bh0, bh1);
                mma16816(acc[1][2*j][0], acc[1][2*j][1], acc[1][2*j][2], acc[1][2*j][3],
                         ag0, ag1, ag2, ag3, bl0, bl1);
                mma16816(acc[1][2*j][0], acc[1][2*j][1], acc[1][2*j][2], acc[1][2*j][3],
                         am0, am1, am2, am3, bh0, bh1);
                mma16816(acc[1][2*j+1][0], acc[1][2*j+1][1], acc[1][2*j+1][2], acc[1][2*j+1][3],
                         ag0, ag1, ag2, ag3, bh2, bh3);
                mma16816(acc[1][2*j+1][0], acc[1][2*j+1][1], acc[1][2*j+1][2], acc[1][2*j+1][3],
                         ag0, ag1, ag2, ag3, bl2, bl3);
                mma16816(acc[1][2*j+1][0], acc[1][2*j+1][1], acc[1][2*j+1][2], acc[1][2*j+1][3],
                         am0, am1, am2, am3, bh2, bh3);
            }
        }
    }

    // ---- epilogue -----------------------------------------------------------
    const float s2 = 0.70710678118654752f;
    const float* bb = bias + (size_t)e * NDIM;
#pragma unroll
    for (int mi = 0; mi < 2; mi++) {
#pragma unroll
        for (int h = 0; h < 2; h++) {
            int row = row0 + wm * 32 + mi * 16 + (l >> 2) + h * 8;
            if (row >= nrows) continue;
#pragma unroll
            for (int nj = 0; nj < 8; nj++) {
                int coln = col0 + wn * 64 + nj * 8 + (l & 3) * 2;
                float v0 = acc[mi][nj][h * 2 + 0] + bb[coln];
                float v1 = acc[mi][nj][h * 2 + 1] + bb[coln + 1];
                if (MODE == 0) {
                    v0 = 0.5f * v0 * (1.0f + erff(v0 * s2));
                    v1 = 0.5f * v1 * (1.0f + erff(v1 * s2));
                    size_t idx = (size_t)(e * CAP + row) * HH + coln;
                    float2 o2 = {v0, v1};
                    *reinterpret_cast<float2*>(&g_Hbuf[idx]) = o2;
                } else {
                    size_t idx = (size_t)(e * CAP + row) * DD + coln;
                    float2 o2 = {v0, v1};
                    *reinterpret_cast<float2*>(&g_Ybuf[idx]) = o2;
                }
            }
        }
    }
}

// ---------------- combine ----------------------------------------------------
__global__ void combine_kernel(float* __restrict__ out) {
    int t = blockIdx.x;
    int d = threadIdx.x * 4;
    int l0 = g_slot[2 * t], l1 = g_slot[2 * t + 1];
    float g0 = g_gate[2 * t], g1 = g_gate[2 * t + 1];
    float4 r = {0.f, 0.f, 0.f, 0.f};
    if (l0 >= 0) {
        float4 y = *(const float4*)(g_Ybuf + (size_t)l0 * DD + d);
        r.x += g0 * y.x; r.y += g0 * y.y; r.z += g0 * y.z; r.w += g0 * y.w;
    }
    if (l1 >= 0) {
        float4 y = *(const float4*)(g_Ybuf + (size_t)l1 * DD + d);
        r.x += g1 * y.x; r.y += g1 * y.y; r.z += g1 * y.z; r.w += g1 * y.w;
    }
    *(float4*)(out + (size_t)t * DD + d) = r;
}

// ---------------- launch -----------------------------------------------------
extern "C" void kernel_launch(void* const* d_in, const int* in_sizes, int n_in,
                              void* d_out, int out_size) {
    (void)in_sizes; (void)n_in; (void)out_size;
    const float* x  = (const float*)d_in[0];
    const float* Wr = (const float*)d_in[1];
    const float* w1 = (const float*)d_in[2];
    const float* b1 = (const float*)d_in[3];
    const float* w2 = (const float*)d_in[4];
    const float* b2 = (const float*)d_in[5];
    float* out = (float*)d_out;

    cudaFuncSetAttribute(moe_gemm<0>, cudaFuncAttributeMaxDynamicSharedMemorySize, GEMM_SMEM);
    cudaFuncSetAttribute(moe_gemm<1>, cudaFuncAttributeMaxDynamicSharedMemorySize, GEMM_SMEM);

    router_kernel<<<NTOK / 8, 256>>>(x, Wr);
    assign_kernel<<<1, ATH>>>();
    moe_gemm<0><<<dim3(HH / 256, CAP / 128, EE), 512, GEMM_SMEM>>>(x, w1, b1);
    moe_gemm<1><<<dim3(DD / 256, CAP / 128, EE), 512, GEMM_SMEM>>>(nullptr, w2, b2);
    combine_kernel<<<NTOK, DD / 4>>>(out);
}

// round 9
// speedup vs baseline: 2.2739x; 1.0645x over previous
#include <cuda_runtime.h>
#include <cuda_bf16.h>
#include <math.h>
#include <stdint.h>

// Problem constants
#define BZ 4
#define SZ 2048
#define DD 768
#define HH 3072
#define EE 8
#define NTOK (BZ*SZ)          // 8192
#define NENT (NTOK*2)         // 16384
#define CAP  1536
#define ROWS_MAX (EE*CAP)     // 12288

// ---------------- device scratch (same footprint as passing R7/R8) ----------
__device__ int   g_topk_e[NENT];
__device__ float g_topk_p[NENT];
__device__ int   g_rows[ROWS_MAX];
__device__ int   g_cnt[EE];
__device__ int   g_slot[NENT];
__device__ float g_gate[NENT];
__device__ float g_Hbuf[(size_t)ROWS_MAX * HH];   // 151 MB
__device__ float g_Ybuf[(size_t)ROWS_MAX * DD];   // 37.7 MB

// ---------------- PTX helpers -----------------------------------------------
__device__ __forceinline__ uint32_t smem_u32(const void* p) {
    uint32_t a;
    asm("{ .reg .u64 t; cvta.to.shared.u64 t, %1; cvt.u32.u64 %0, t; }" : "=r"(a) : "l"(p));
    return a;
}
__device__ __forceinline__ void ldsm4(uint32_t& r0, uint32_t& r1, uint32_t& r2, uint32_t& r3,
                                      uint32_t addr) {
    asm volatile("ldmatrix.sync.aligned.m8n8.x4.shared.b16 {%0,%1,%2,%3}, [%4];"
                 : "=r"(r0), "=r"(r1), "=r"(r2), "=r"(r3) : "r"(addr));
}
__device__ __forceinline__ void ldsm4t(uint32_t& r0, uint32_t& r1, uint32_t& r2, uint32_t& r3,
                                       uint32_t addr) {
    asm volatile("ldmatrix.sync.aligned.m8n8.x4.trans.shared.b16 {%0,%1,%2,%3}, [%4];"
                 : "=r"(r0), "=r"(r1), "=r"(r2), "=r"(r3) : "r"(addr));
}
__device__ __forceinline__ void mma16816(float& c0, float& c1, float& c2, float& c3,
                                         uint32_t a0, uint32_t a1, uint32_t a2, uint32_t a3,
                                         uint32_t b0, uint32_t b1) {
    asm volatile("mma.sync.aligned.m16n8k16.row.col.f32.bf16.bf16.f32 "
                 "{%0,%1,%2,%3}, {%4,%5,%6,%7}, {%8,%9}, {%0,%1,%2,%3};"
                 : "+f"(c0), "+f"(c1), "+f"(c2), "+f"(c3)
                 : "r"(a0), "r"(a1), "r"(a2), "r"(a3), "r"(b0), "r"(b1));
}
__device__ __forceinline__ void split2(float f0, float f1, uint32_t& hi, uint32_t& lo) {
    __nv_bfloat16 h0 = __float2bfloat16(f0), h1 = __float2bfloat16(f1);
    __nv_bfloat16 l0 = __float2bfloat16(f0 - __bfloat162float(h0));
    __nv_bfloat16 l1 = __float2bfloat16(f1 - __bfloat162float(h1));
    hi = (uint32_t)*(unsigned short*)&h0 | ((uint32_t)*(unsigned short*)&h1 << 16);
    lo = (uint32_t)*(unsigned short*)&l0 | ((uint32_t)*(unsigned short*)&l1 << 16);
}

// ---------------- router -----------------------------------------------------
__global__ void router_kernel(const float* __restrict__ x,
                              const float* __restrict__ Wr) {
    int warp = threadIdx.x >> 5;
    int lane = threadIdx.x & 31;
    int t = blockIdx.x * 8 + warp;
    if (t >= NTOK) return;
    const float* xr = x + (size_t)t * DD;
    float acc[EE];
#pragma unroll
    for (int e = 0; e < EE; e++) acc[e] = 0.f;
    for (int i = lane; i < DD; i += 32) {
        float xv = xr[i];
        const float4* wr4 = reinterpret_cast<const float4*>(Wr + i * EE);
        float4 w0 = wr4[0], w1 = wr4[1];
        acc[0] += xv * w0.x; acc[1] += xv * w0.y;
        acc[2] += xv * w0.z; acc[3] += xv * w0.w;
        acc[4] += xv * w1.x; acc[5] += xv * w1.y;
        acc[6] += xv * w1.z; acc[7] += xv * w1.w;
    }
#pragma unroll
    for (int e = 0; e < EE; e++)
#pragma unroll
        for (int o = 16; o > 0; o >>= 1)
            acc[e] += __shfl_xor_sync(0xffffffffu, acc[e], o);
    if (lane == 0) {
        float m = acc[0];
#pragma unroll
        for (int e = 1; e < EE; e++) m = fmaxf(m, acc[e]);
        float p[EE]; float s = 0.f;
#pragma unroll
        for (int e = 0; e < EE; e++) { p[e] = expf(acc[e] - m); s += p[e]; }
        float inv = 1.f / s;
#pragma unroll
        for (int e = 0; e < EE; e++) p[e] *= inv;
        int i0 = 0;
#pragma unroll
        for (int e = 1; e < EE; e++) if (p[e] > p[i0]) i0 = e;
        int i1 = -1;
#pragma unroll
        for (int e = 0; e < EE; e++) {
            if (e == i0) continue;
            if (i1 < 0 || p[e] > p[i1]) i1 = e;
        }
        float ps = 1.f / (p[i0] + p[i1]);
        g_topk_e[2 * t + 0] = i0; g_topk_p[2 * t + 0] = p[i0] * ps;
        g_topk_e[2 * t + 1] = i1; g_topk_p[2 * t + 1] = p[i1] * ps;
    }
}

// ---------------- capacity assignment (exact flat-order) ---------------------
#define ATH 512
#define EPT (NENT / ATH)
__global__ void assign_kernel() {
    __shared__ int sh[EE][ATH];
    int t = threadIdx.x;
    int loc[EE];
#pragma unroll
    for (int e = 0; e < EE; e++) loc[e] = 0;
    int start = t * EPT;
    for (int i = 0; i < EPT; i++) {
        int ev = g_topk_e[start + i];
#pragma unroll
        for (int e = 0; e < EE; e++) loc[e] += (ev == e);
    }
#pragma unroll
    for (int e = 0; e < EE; e++) sh[e][t] = loc[e];
    __syncthreads();
    if (t < EE) {
        int run = 0;
        for (int i = 0; i < ATH; i++) { int v = sh[t][i]; sh[t][i] = run; run += v; }
        g_cnt[t] = run < CAP ? run : CAP;
    }
    __syncthreads();
    int off[EE];
#pragma unroll
    for (int e = 0; e < EE; e++) off[e] = sh[e][t];
    for (int i = 0; i < EPT; i++) {
        int idx = start + i;
        int ev = g_topk_e[idx];
        int pos = 0;
#pragma unroll
        for (int e = 0; e < EE; e++) {
            if (ev == e) { pos = off[e]; off[e] = pos + 1; }
        }
        if (pos < CAP) {
            g_rows[ev * CAP + pos] = idx >> 1;
            g_slot[idx] = ev * CAP + pos;
            g_gate[idx] = g_topk_p[idx];
        } else {
            g_slot[idx] = -1;
            g_gate[idx] = 0.f;
        }
    }
}

// ---------------- HMMA grouped GEMM: 128x96 tile, 256 thr, 2 CTAs/SM --------
// 8 warps (4m x 2n), warp tile 32x48, K-tile 32, double-buffered,
// one barrier per K-tile; two CTAs per SM give independent barrier domains.
// A smem: [128 m][32 k] bf16, row 80 B (hi & lo planes).
// B smem: [32 k][96 n] bf16, row 208 B (hi & lo planes), ldmatrix.trans.
#define AROW 80
#define BROW 208
#define APL  (128 * AROW)              // 10240 B
#define BPL  (32 * BROW)               // 6656 B
#define BUFB (2 * APL + 2 * BPL)       // 33792 B per buffer
#define GEMM_SMEM (2 * BUFB)           // 67584 B per CTA

template <int MODE>
__global__ void __launch_bounds__(256, 2) moe_gemm(const float* __restrict__ X,
                                                   const float* __restrict__ W,
                                                   const float* __restrict__ bias) {
    constexpr int KDIM = (MODE == 0) ? DD : HH;
    constexpr int NDIM = (MODE == 0) ? HH : DD;
    constexpr int NT = KDIM / 32;
    extern __shared__ char smem[];

    const int e = blockIdx.z;
    const int nrows = g_cnt[e];
    const int row0 = blockIdx.y * 128;
    if (row0 >= nrows) return;
    const int col0 = blockIdx.x * 96;
    const int tid = threadIdx.x;
    const int l = tid & 31, wid = tid >> 5;
    const int wm = wid & 3, wn = wid >> 2;        // 4x2 warps: 32m x 48n each
    const uint32_t sb0 = smem_u32(smem);

    // ---- loader indices ----------------------------------------------------
    // A: 1024 16B chunks, 4/thread: rows am+32g, 16B col akc
    const int am = tid >> 3, akc = tid & 7;
    const float* pA[4];
#pragma unroll
    for (int g = 0; g < 4; g++) {
        if (MODE == 0) {
            int tok = g_rows[e * CAP + row0 + am + 32 * g] & (NTOK - 1);
            pA[g] = X + (size_t)tok * DD + akc * 4;
        } else {
            pA[g] = g_Hbuf + (size_t)(e * CAP + row0 + am + 32 * g) * HH + akc * 4;
        }
    }
    // B: 768 16B chunks (32 k-rows x 24), 3/thread
    int bRow[3], bCol[3];
#pragma unroll
    for (int t = 0; t < 3; t++) {
        int c = tid + t * 256;
        bRow[t] = c / 24; bCol[t] = c % 24;
    }
    const float* Wb = W + (size_t)e * KDIM * NDIM;
    const float* pB[3];
#pragma unroll
    for (int t = 0; t < 3; t++)
        pB[t] = Wb + (size_t)bRow[t] * NDIM + col0 + bCol[t] * 4;
    const uint32_t sA = (uint32_t)(am * AROW + akc * 8);
    uint32_t sB[3];
#pragma unroll
    for (int t = 0; t < 3; t++)
        sB[t] = (uint32_t)(bRow[t] * BROW + bCol[t] * 8);

    // ---- fragment lane offsets ---------------------------------------------
    const uint32_t offA = (uint32_t)((wm * 32 + (l & 15)) * AROW + ((l >> 4) & 1) * 16);
    const uint32_t offBt = (uint32_t)((((l & 7) + ((l >> 3) & 1) * 8)) * BROW
                                      + (l >> 4) * 16 + wn * 96);     // wn*48 cols * 2B

    float acc[2][6][4];
#pragma unroll
    for (int mi = 0; mi < 2; mi++)
#pragma unroll
        for (int nj = 0; nj < 6; nj++)
#pragma unroll
            for (int q = 0; q < 4; q++) acc[mi][nj][q] = 0.f;

    // ---- prefetch tile 0 ----------------------------------------------------
    float4 aS[4], bS[3];
#pragma unroll
    for (int g = 0; g < 4; g++) aS[g] = *(const float4*)pA[g];
#pragma unroll
    for (int t = 0; t < 3; t++) bS[t] = *(const float4*)pB[t];

    for (int kt = 0; kt < NT; kt++) {
        char* buf = smem + (kt & 1) * BUFB;
        // ---- split + store current tile ------------------------------------
        {
            uint32_t h0, v0, h1, v1;
#pragma unroll
            for (int g = 0; g < 4; g++) {
                split2(aS[g].x, aS[g].y, h0, v0); split2(aS[g].z, aS[g].w, h1, v1);
                *(uint2*)(buf + sA + g * 32 * AROW)       = make_uint2(h0, h1);
                *(uint2*)(buf + APL + sA + g * 32 * AROW) = make_uint2(v0, v1);
            }
#pragma unroll
            for (int t = 0; t < 3; t++) {
                split2(bS[t].x, bS[t].y, h0, v0); split2(bS[t].z, bS[t].w, h1, v1);
                *(uint2*)(buf + 2 * APL + sB[t])       = make_uint2(h0, h1);
                *(uint2*)(buf + 2 * APL + BPL + sB[t]) = make_uint2(v0, v1);
            }
        }
        // ---- prefetch next tile --------------------------------------------
        if (kt + 1 < NT) {
            size_t ka = (size_t)(kt + 1) * 32;
            size_t kb = (size_t)(kt + 1) * 32 * NDIM;
#pragma unroll
            for (int g = 0; g < 4; g++) aS[g] = *(const float4*)(pA[g] + ka);
#pragma unroll
            for (int t = 0; t < 3; t++) bS[t] = *(const float4*)(pB[t] + kb);
        }
        __syncthreads();   // single barrier per K-tile (double-buffer safe)
        // ---- compute on this buffer ----------------------------------------
        const uint32_t sbA = sb0 + (kt & 1) * BUFB;
        const uint32_t sbB = sbA + 2 * APL;
#pragma unroll
        for (int k16 = 0; k16 < 2; k16++) {
            const uint32_t kbA = k16 * 32;
            const uint32_t kbB = k16 * 16 * BROW;
            uint32_t ah0, ah1, ah2, ah3, ag0, ag1, ag2, ag3;
            uint32_t al0, al1, al2, al3, am0, am1, am2, am3;
            ldsm4(ah0, ah1, ah2, ah3, sbA + offA + kbA);
            ldsm4(ag0, ag1, ag2, ag3, sbA + offA + 16 * AROW + kbA);
            ldsm4(al0, al1, al2, al3, sbA + APL + offA + kbA);
            ldsm4(am0, am1, am2, am3, sbA + APL + offA + 16 * AROW + kbA);
#pragma unroll
            for (int j = 0; j < 3; j++) {          // three n16 groups (48 cols)
                uint32_t bh0, bh1, bh2, bh3, bl0, bl1, bl2, bl3;
                ldsm4t(bh0, bh1, bh2, bh3, sbB + offBt + kbB + j * 32);
                ldsm4t(bl0, bl1, bl2, bl3, sbB + BPL + offBt + kbB + j * 32);
                mma16816(acc[0][2*j][0], acc[0][2*j][1], acc[0][2*j][2], acc[0][2*j][3],
                         ah0, ah1, ah2, ah3, bh0, bh1);
                mma16816(acc[0][2*j][0], acc[0][2*j][1], acc[0][2*j][2], acc[0][2*j][3],
                         ah0, ah1, ah2, ah3, bl0, bl1);
                mma16816(acc[0][2*j][0], acc[0][2*j][1], acc[0][2*j][2], acc[0][2*j][3],
                         al0, al1, al2, al3, bh0, bh1);
                mma16816(acc[0][2*j+1][0], acc[0][2*j+1][1], acc[0][2*j+1][2], acc[0][2*j+1][3],
                         ah0, ah1, ah2, ah3, bh2, bh3);
                mma16816(acc[0][2*j+1][0], acc[0][2*j+1][1], acc[0][2*j+1][2], acc[0][2*j+1][3],
                         ah0, ah1, ah2, ah3, bl2, bl3);
                mma16816(acc[0][2*j+1][0], acc[0][2*j+1][1], acc[0][2*j+1][2], acc[0][2*j+1][3],
                         al0, al1, al2, al3, bh2, bh3);
                mma16816(acc[1][2*j][0], acc[1][2*j][1], acc[1][2*j][2], acc[1][2*j][3],
                         ag0, ag1, ag2, ag3, bh0, bh1);
                mma16816(acc[1][2*j][0], acc[1][2*j][1], acc[1][2*j][2], acc[1][2*j][3],
                         ag0, ag1, ag2, ag3, bl0, bl1);
                mma16816(acc[1][2*j][0], acc[1][2*j][1], acc[1][2*j][2], acc[1][2*j][3],
                         am0, am1, am2, am3, bh0, bh1);
                mma16816(acc[1][2*j+1][0], acc[1][2*j+1][1], acc[1][2*j+1][2], acc[1][2*j+1][3],
                         ag0, ag1, ag2, ag3, bh2, bh3);
                mma16816(acc[1][2*j+1][0], acc[1][2*j+1][1], acc[1][2*j+1][2], acc[1][2*j+1][3],
                         ag0, ag1, ag2, ag3, bl2, bl3);
                mma16816(acc[1][2*j+1][0], acc[1][2*j+1][1], acc[1][2*j+1][2], acc[1][2*j+1][3],
                         am0, am1, am2, am3, bh2, bh3);
            }
        }
    }

    // ---- epilogue -----------------------------------------------------------
    const float s2 = 0.70710678118654752f;
    const float* bb = bias + (size_t)e * NDIM;
#pragma unroll
    for (int mi = 0; mi < 2; mi++) {
#pragma unroll
        for (int h = 0; h < 2; h++) {
            int row = row0 + wm * 32 + mi * 16 + (l >> 2) + h * 8;
            if (row >= nrows) continue;
#pragma unroll
            for (int nj = 0; nj < 6; nj++) {
                int coln = col0 + wn * 48 + nj * 8 + (l & 3) * 2;
                float v0 = acc[mi][nj][h * 2 + 0] + bb[coln];
                float v1 = acc[mi][nj][h * 2 + 1] + bb[coln + 1];
                if (MODE == 0) {
                    v0 = 0.5f * v0 * (1.0f + erff(v0 * s2));
                    v1 = 0.5f * v1 * (1.0f + erff(v1 * s2));
                    size_t idx = (size_t)(e * CAP + row) * HH + coln;
                    float2 o2 = {v0, v1};
                    *reinterpret_cast<float2*>(&g_Hbuf[idx]) = o2;
                } else {
                    size_t idx = (size_t)(e * CAP + row) * DD + coln;
                    float2 o2 = {v0, v1};
                    *reinterpret_cast<float2*>(&g_Ybuf[idx]) = o2;
                }
            }
        }
    }
}

// ---------------- combine ----------------------------------------------------
__global__ void combine_kernel(float* __restrict__ out) {
    int t = blockIdx.x;
    int d = threadIdx.x * 4;
    int l0 = g_slot[2 * t], l1 = g_slot[2 * t + 1];
    float g0 = g_gate[2 * t], g1 = g_gate[2 * t + 1];
    float4 r = {0.f, 0.f, 0.f, 0.f};
    if (l0 >= 0) {
        float4 y = *(const float4*)(g_Ybuf + (size_t)l0 * DD + d);
        r.x += g0 * y.x; r.y += g0 * y.y; r.z += g0 * y.z; r.w += g0 * y.w;
    }
    if (l1 >= 0) {
        float4 y = *(const float4*)(g_Ybuf + (size_t)l1 * DD + d);
        r.x += g1 * y.x; r.y += g1 * y.y; r.z += g1 * y.z; r.w += g1 * y.w;
    }
    *(float4*)(out + (size_t)t * DD + d) = r;
}

// ---------------- launch -----------------------------------------------------
extern "C" void kernel_launch(void* const* d_in, const int* in_sizes, int n_in,
                              void* d_out, int out_size) {
    (void)in_sizes; (void)n_in; (void)out_size;
    const float* x  = (const float*)d_in[0];
    const float* Wr = (const float*)d_in[1];
    const float* w1 = (const float*)d_in[2];
    const float* b1 = (const float*)d_in[3];
    const float* w2 = (const float*)d_in[4];
    const float* b2 = (const float*)d_in[5];
    float* out = (float*)d_out;

    cudaFuncSetAttribute(moe_gemm<0>, cudaFuncAttributeMaxDynamicSharedMemorySize, GEMM_SMEM);
    cudaFuncSetAttribute(moe_gemm<1>, cudaFuncAttributeMaxDynamicSharedMemorySize, GEMM_SMEM);

    router_kernel<<<NTOK / 8, 256>>>(x, Wr);
    assign_kernel<<<1, ATH>>>();
    moe_gemm<0><<<dim3(HH / 96, CAP / 128, EE), 256, GEMM_SMEM>>>(x, w1, b1);
    moe_gemm<1><<<dim3(DD / 96, CAP / 128, EE), 256, GEMM_SMEM>>>(nullptr, w2, b2);
    combine_kernel<<<NTOK, DD / 4>>>(out);
}